// round 6
// baseline (speedup 1.0000x reference)
#include <cuda_runtime.h>
#include <cuda_bf16.h>
#include <cstdint>
#include <math.h>

#define NB 256
#define NS 32
#define NL 32
#define ND 256
#define NE 64
#define KBIG 768          // concatenated K: [hi | hi | lo] x [Hi ; Lo ; Hi]

// ===================== scratch (device globals; no runtime alloc) =====================
__device__ float g_enc[NB*NS*ND];            // enc[b,s,d]
__device__ float g_eW [NB*NS*ND];            // enc @ W
__device__ float g_kV [NB*NE*ND];            // keys @ V
__device__ int   g_act[NB*NS];
__device__ __nv_bfloat16 g_Ut[ND*KBIG];      // U^T  [Hi|Lo|Hi]
__device__ __nv_bfloat16 g_Vt[ND*KBIG];      // V^T  [Hi|Lo|Hi]
__device__ __nv_bfloat16 g_Wt[ND*KBIG];      // W^T  [Hi|Lo|Hi]
__device__ __nv_bfloat16 g_kyhi[NB*NE*ND];   // keys split
__device__ __nv_bfloat16 g_kylo[NB*NE*ND];
__device__ __nv_bfloat16 g_enhi[NB*NS*ND];   // enc split
__device__ __nv_bfloat16 g_enlo[NB*NS*ND];
__device__ __nv_bfloat16 g_hA_hi[NB*NE*ND];  // h split hi (row,k)
__device__ __nv_bfloat16 g_hA_lo[NB*NE*ND];  // h split lo

// ===================== PTX wrappers (sm_80-level features only) =====================
__device__ __forceinline__ uint32_t smem_u32(const void* p) {
    uint32_t a;
    asm("{ .reg .u64 t; cvta.to.shared.u64 t, %1; cvt.u32.u64 %0, t; }" : "=r"(a) : "l"(p));
    return a;
}
__device__ __forceinline__ void cpa16(uint32_t dst, const void* src) {
    asm volatile("cp.async.cg.shared.global [%0], [%1], 16;" :: "r"(dst), "l"(src));
}
#define CP_COMMIT() asm volatile("cp.async.commit_group;" ::: "memory")
#define CP_WAIT1()  asm volatile("cp.async.wait_group 1;"  ::: "memory")
#define CP_WAIT0()  asm volatile("cp.async.wait_group 0;"  ::: "memory")

__device__ __forceinline__ void ldsm_x4(uint32_t* r, uint32_t addr) {
    asm volatile("ldmatrix.sync.aligned.m8n8.x4.shared.b16 {%0,%1,%2,%3}, [%4];"
        : "=r"(r[0]), "=r"(r[1]), "=r"(r[2]), "=r"(r[3]) : "r"(addr));
}
__device__ __forceinline__ void ldsm_x2(uint32_t* r, uint32_t addr) {
    asm volatile("ldmatrix.sync.aligned.m8n8.x2.shared.b16 {%0,%1}, [%2];"
        : "=r"(r[0]), "=r"(r[1]) : "r"(addr));
}
__device__ __forceinline__ void mma_bf16(float* d, const uint32_t* a, const uint32_t* b) {
    asm volatile("mma.sync.aligned.m16n8k16.row.col.f32.bf16.bf16.f32 "
        "{%0,%1,%2,%3}, {%4,%5,%6,%7}, {%8,%9}, {%0,%1,%2,%3};"
        : "+f"(d[0]), "+f"(d[1]), "+f"(d[2]), "+f"(d[3])
        : "r"(a[0]), "r"(a[1]), "r"(a[2]), "r"(a[3]), "r"(b[0]), "r"(b[1]));
}

// ===================== SMEM layout (shared by steps + hmma_gemm0) =====================
#define SM_GATE 0
#define SM_RSQ  512
#define SM_DV   1024
#define SM_DH   1536
#define SM_DK   2048
#define SM_GN   2560
#define SM_ACTS 3072
#define SM_ST0  4096
#define A_TILE_B (128*144)             // rows padded to 144B -> conflict-free ldmatrix
#define B_TILE_B (256*144)
#define STAGE_B  (A_TILE_B + B_TILE_B) // 55296
#define SMEM_BYTES (SM_ST0 + 3*STAGE_B)    // 169984

// ===================== encode (vectorized) =====================
__global__ __launch_bounds__(256)
void encode_kernel(const int* __restrict__ tok, const float* __restrict__ mask,
                   const float* __restrict__ emb) {
    __shared__ float4 red[4][64];
    __shared__ float msum;
    const int bs = blockIdx.x, tid = threadIdx.x;
    const int lg = tid >> 6, d4 = tid & 63;
    const int*   t = tok  + (size_t)bs*NL;
    const float* m = mask + (size_t)bs*NL;

    if (tid < 32) {
        float mv = m[tid];
        #pragma unroll
        for (int o = 16; o > 0; o >>= 1) mv += __shfl_xor_sync(0xffffffffu, mv, o);
        if (tid == 0) { g_act[bs] = (mv > 0.f) ? 1 : 0; msum = mv; }
    }

    float4 acc = make_float4(0.f, 0.f, 0.f, 0.f);
    #pragma unroll
    for (int i = 0; i < 8; i++) {
        int l = lg*8 + i;
        float mv = __ldg(m + l);
        int   tv = __ldg(t + l);
        float4 e = __ldg((const float4*)(emb + (size_t)tv*ND) + d4);
        acc.x += mv*e.x; acc.y += mv*e.y; acc.z += mv*e.z; acc.w += mv*e.w;
    }
    red[lg][d4] = acc;
    __syncthreads();
    if (lg == 0) {
        float4 a = red[0][d4], b = red[1][d4], c = red[2][d4], d = red[3][d4];
        ((float4*)(g_enc + (size_t)bs*ND))[d4] =
            make_float4(a.x+b.x+c.x+d.x, a.y+b.y+c.y+d.y, a.z+b.z+c.z+d.z, a.w+b.w+c.w+d.w);
    }
}

// ===================== prep: Mt[n][k] = [Mhi^T | Mlo^T | Mhi^T], all 3 matrices ======
__global__ void prep_bt_all(const float* __restrict__ U, const float* __restrict__ V,
                            const float* __restrict__ W) {
    int n = blockIdx.x & 255, which = blockIdx.x >> 8, k = threadIdx.x;
    const float* M = (which == 0) ? U : (which == 1) ? V : W;
    __nv_bfloat16* out = (which == 0) ? g_Ut : (which == 1) ? g_Vt : g_Wt;
    float v = M[(size_t)k*ND + n];
    __nv_bfloat16 hi = __float2bfloat16(v);
    __nv_bfloat16 lo = __float2bfloat16(v - __bfloat162float(hi));
    out[(size_t)n*KBIG + k]       = hi;
    out[(size_t)n*KBIG + 256 + k] = lo;
    out[(size_t)n*KBIG + 512 + k] = hi;
}

// ===================== split fp32 -> bf16 hi/lo (keys and enc) =====================
__global__ void split_kernel(const float* __restrict__ keys) {
    int i = blockIdx.x * blockDim.x + threadIdx.x;       // over 6.29M elems
    const int NK = NB*NE*ND;
    float v; __nv_bfloat16 *ph, *pl; int idx;
    if (i < NK) { v = keys[i]; ph = g_kyhi; pl = g_kylo; idx = i; }
    else        { idx = i - NK; v = g_enc[idx]; ph = g_enhi; pl = g_enlo; }
    __nv_bfloat16 h = __float2bfloat16(v);
    ph[idx] = h;
    pl[idx] = __float2bfloat16(v - __bfloat162float(h));
}

// ===================== HMMA prelude GEMM: kV = keys@V and eW = enc@W ================
__global__ void __launch_bounds__(512, 1)
hmma_gemm0() {
    extern __shared__ char smem[];
    const uint32_t sb = smem_u32(smem);
    const int tid  = threadIdx.x;
    const int lane = tid & 31;
    const int wid  = tid >> 5;
    const int warp_m = wid >> 2, warp_n = wid & 3;
    const int bx = blockIdx.x;

    const __nv_bfloat16 *Ahi, *Alo, *Bt; float* C; int rowBase;
    if (bx < 128) { Ahi = g_kyhi; Alo = g_kylo; Bt = g_Vt; C = g_kV; rowBase = bx*128; }
    else          { Ahi = g_enhi; Alo = g_enlo; Bt = g_Wt; C = g_eW; rowBase = (bx-128)*128; }
    const __nv_bfloat16* hi = Ahi + (size_t)rowBase*ND;
    const __nv_bfloat16* lo = Alo + (size_t)rowBase*ND;

    const int selA = lane >> 3;
    const uint32_t aoff = (uint32_t)(((selA & 1)*8 + (lane & 7))*144 + (selA >> 1)*16);
    const int l16 = lane & 15;
    const uint32_t boff = (uint32_t)((l16 & 7)*144 + (l16 >> 3)*16);

    auto load_chunk = [&](int c, int slot) {
        const __nv_bfloat16* asrc = ((c < 8) ? hi : lo) + (c & 3)*64;
        const __nv_bfloat16* bsrc = Bt + c*64;
        uint32_t adst = sb + SM_ST0 + (uint32_t)slot*STAGE_B;
        uint32_t bdst = adst + A_TILE_B;
        #pragma unroll
        for (int i = 0; i < 2; i++) {
            int idx = tid + i*512, row = idx >> 3, seg = idx & 7;
            cpa16(adst + row*144 + seg*16, asrc + (size_t)row*ND + seg*8);
        }
        #pragma unroll
        for (int i = 0; i < 4; i++) {
            int idx = tid + i*512, n = idx >> 3, seg = idx & 7;
            cpa16(bdst + n*144 + seg*16, bsrc + (size_t)n*KBIG + seg*8);
        }
    };

    float acc[2][8][4];
    #pragma unroll
    for (int mt = 0; mt < 2; mt++)
        #pragma unroll
        for (int nt = 0; nt < 8; nt++)
            #pragma unroll
            for (int q = 0; q < 4; q++) acc[mt][nt][q] = 0.f;

    load_chunk(0, 0); CP_COMMIT();
    load_chunk(1, 1); CP_COMMIT();
    #pragma unroll
    for (int c = 0; c < 12; ++c) {
        if (c < 11) CP_WAIT1(); else CP_WAIT0();
        __syncthreads();
        if (c < 10) { load_chunk(c + 2, (c + 2) % 3); CP_COMMIT(); }
        const uint32_t base = sb + SM_ST0 + (uint32_t)(c % 3)*STAGE_B;
        const uint32_t abase = base + (warp_m*32)*144 + aoff;
        const uint32_t bbase = base + A_TILE_B + (warp_n*64)*144 + boff;
        #pragma unroll
        for (int k4 = 0; k4 < 4; ++k4) {
            const uint32_t kb = k4 * 32;
            uint32_t a0[4], a1[4];
            ldsm_x4(a0, abase + kb);
            ldsm_x4(a1, abase + 16*144 + kb);
            #pragma unroll
            for (int nt = 0; nt < 8; ++nt) {
                uint32_t bfrag[2];
                ldsm_x2(bfrag, bbase + nt*8*144 + kb);
                mma_bf16(acc[0][nt], a0, bfrag);
                mma_bf16(acc[1][nt], a1, bfrag);
            }
        }
        __syncthreads();
    }

    #pragma unroll
    for (int mt = 0; mt < 2; mt++) {
        int rA = warp_m*32 + mt*16 + (lane >> 2);
        int rB = rA + 8;
        size_t gOA = (size_t)(rowBase + rA)*ND;
        size_t gOB = (size_t)(rowBase + rB)*ND;
        #pragma unroll
        for (int nt = 0; nt < 8; nt++) {
            int col = warp_n*64 + nt*8 + 2*(lane & 3);
            *(float2*)(C + gOA + col) = make_float2(acc[mt][nt][0], acc[mt][nt][1]);
            *(float2*)(C + gOB + col) = make_float2(acc[mt][nt][2], acc[mt][nt][3]);
        }
    }
}

// ===================== persistent fused recurrence: all 32 steps in one launch =======
__global__ void __launch_bounds__(512, 1)
steps_kernel(const float* __restrict__ keys, float* __restrict__ h) {
    extern __shared__ char smem[];
    const uint32_t sb = smem_u32(smem);
    const int tid    = threadIdx.x;
    const int lane   = tid & 31;
    const int wid    = tid >> 5;
    const int warp_m = wid >> 2;          // 0..3 -> 32 rows each
    const int warp_n = wid & 3;           // 0..3 -> 64 cols each
    const int rowBase = blockIdx.x * 128;

    float* gs   = (float*)(smem + SM_GATE);
    float* rs   = (float*)(smem + SM_RSQ);
    float* dV   = (float*)(smem + SM_DV);
    float* dH   = (float*)(smem + SM_DH);
    float* dK   = (float*)(smem + SM_DK);
    float* gn   = (float*)(smem + SM_GN);
    int*   acts = (int*)  (smem + SM_ACTS);

    // ---------- phase 0: gn = dot(enc_0, keys_row)  (h=0 at s=0) ----------
    {
        int r = tid >> 2, part = tid & 3;
        int grow = rowBase + r;
        int b = grow >> 6;
        const float4* e4 = (const float4*)(g_enc + ((size_t)b*NS)*ND + part*64);
        const float4* k4 = (const float4*)(keys + (size_t)grow*ND + part*64);
        float d = 0.f;
        #pragma unroll
        for (int i = 0; i < 16; i++) {
            float4 e = e4[i], kv = k4[i];
            d += e.x*kv.x + e.y*kv.y + e.z*kv.z + e.w*kv.w;
        }
        d += __shfl_xor_sync(0xffffffffu, d, 1);
        d += __shfl_xor_sync(0xffffffffu, d, 2);
        if (part == 0) gn[r] = d;
    }

    const __nv_bfloat16* hi = g_hA_hi + (size_t)rowBase*ND;
    const __nv_bfloat16* lo = g_hA_lo + (size_t)rowBase*ND;

    const int selA = lane >> 3;
    const uint32_t aoff = (uint32_t)(((selA & 1)*8 + (lane & 7))*144 + (selA >> 1)*16);
    const int l16 = lane & 15;
    const uint32_t boff = (uint32_t)((l16 & 7)*144 + (l16 >> 3)*16);

    auto load_chunk = [&](int c, int slot) {
        const __nv_bfloat16* asrc = ((c < 8) ? hi : lo) + (c & 3)*64;
        const __nv_bfloat16* bsrc = g_Ut + c*64;
        uint32_t adst = sb + SM_ST0 + (uint32_t)slot*STAGE_B;
        uint32_t bdst = adst + A_TILE_B;
        #pragma unroll
        for (int i = 0; i < 2; i++) {
            int idx = tid + i*512, row = idx >> 3, seg = idx & 7;
            cpa16(adst + row*144 + seg*16, asrc + (size_t)row*ND + seg*8);
        }
        #pragma unroll
        for (int i = 0; i < 4; i++) {
            int idx = tid + i*512, n = idx >> 3, seg = idx & 7;
            cpa16(bdst + n*144 + seg*16, bsrc + (size_t)n*KBIG + seg*8);
        }
    };

    for (int s = 0; s < NS; ++s) {
        const bool first = (s == 0);
        __syncthreads();                  // prev pass2 (and phase0) done
        if (tid < 128) {
            int grow = rowBase + tid;
            int b = grow >> 6;
            gs[tid]   = 1.f / (1.f + expf(-gn[tid]));
            acts[tid] = g_act[b*NS + s];
            rs[tid] = 0.f; dV[tid] = 0.f; dH[tid] = 0.f; dK[tid] = 0.f;
        }

        float acc[2][8][4];
        #pragma unroll
        for (int mt = 0; mt < 2; mt++)
            #pragma unroll
            for (int nt = 0; nt < 8; nt++)
                #pragma unroll
                for (int q = 0; q < 4; q++) acc[mt][nt][q] = 0.f;

        if (!first) {
            load_chunk(0, 0); CP_COMMIT();
            load_chunk(1, 1); CP_COMMIT();
            #pragma unroll
            for (int c = 0; c < 12; ++c) {
                if (c < 11) CP_WAIT1(); else CP_WAIT0();
                __syncthreads();
                if (c < 10) { load_chunk(c + 2, (c + 2) % 3); CP_COMMIT(); }
                const uint32_t base = sb + SM_ST0 + (uint32_t)(c % 3)*STAGE_B;
                const uint32_t abase = base + (warp_m*32)*144 + aoff;
                const uint32_t bbase = base + A_TILE_B + (warp_n*64)*144 + boff;
                #pragma unroll
                for (int k4 = 0; k4 < 4; ++k4) {
                    const uint32_t kb = k4 * 32;
                    uint32_t a0[4], a1[4];
                    ldsm_x4(a0, abase + kb);
                    ldsm_x4(a1, abase + 16*144 + kb);
                    #pragma unroll
                    for (int nt = 0; nt < 8; ++nt) {
                        uint32_t bfrag[2];
                        ldsm_x2(bfrag, bbase + nt*8*144 + kb);
                        mma_bf16(acc[0][nt], a0, bfrag);
                        mma_bf16(acc[1][nt], a1, bfrag);
                    }
                }
            }
        } else {
            __syncthreads();              // gs/acts visible for epilogue
        }

        // ---------- epilogue pass 1: relu-add, gated update, reductions ----------
        const int sn = (s + 1 < NS) ? s + 1 : NS - 1;
        #pragma unroll
        for (int mt = 0; mt < 2; mt++) {
            int rA = warp_m*32 + mt*16 + (lane >> 2);
            int rB = rA + 8;
            int gA = rowBase + rA, gB = rowBase + rB;
            int bA = gA >> 6;                         // rA,rB same b
            const float* kvA = g_kV + (size_t)gA*ND;
            const float* kvB = g_kV + (size_t)gB*ND;
            const float* ewR = g_eW  + ((size_t)bA*NS + s )*ND;
            const float* enN = g_enc + ((size_t)bA*NS + sn)*ND;
            const float* hA  = h    + (size_t)gA*ND;
            const float* hB  = h    + (size_t)gB*ND;
            const float* kyA = keys + (size_t)gA*ND;
            const float* kyB = keys + (size_t)gB*ND;
            float gateA = gs[rA], gateB = gs[rB];
            float sA = 0.f, sB = 0.f;
            float dVA = 0.f, dVB = 0.f, dHA = 0.f, dHB = 0.f, dKA = 0.f, dKB = 0.f;
            #pragma unroll
            for (int nt = 0; nt < 8; nt++) {
                int col = warp_n*64 + nt*8 + 2*(lane & 3);
                float2 en = *(const float2*)(enN + col);
                float2 ew = *(const float2*)(ewR + col);
                float2 ky, kv, ho;
                ky = *(const float2*)(kyA + col);
                kv = *(const float2*)(kvA + col);
                ho = first ? make_float2(0.f, 0.f) : *(const float2*)(hA + col);
                float v0 = fmaxf(acc[mt][nt][0] + kv.x + ew.x, 0.f);
                float v1 = fmaxf(acc[mt][nt][1] + kv.y + ew.y, 0.f);
                float h0 = ho.x + gateA*v0, h1 = ho.y + gateA*v1;
                acc[mt][nt][0] = h0; acc[mt][nt][1] = h1;
                sA  += h0*h0 + h1*h1;
                dVA += en.x*h0 + en.y*h1;
                dHA += en.x*ho.x + en.y*ho.y;
                dKA += en.x*ky.x + en.y*ky.y;
                ky = *(const float2*)(kyB + col);
                kv = *(const float2*)(kvB + col);
                ho = first ? make_float2(0.f, 0.f) : *(const float2*)(hB + col);
                float w0 = fmaxf(acc[mt][nt][2] + kv.x + ew.x, 0.f);
                float w1 = fmaxf(acc[mt][nt][3] + kv.y + ew.y, 0.f);
                float h2 = ho.x + gateB*w0, h3 = ho.y + gateB*w1;
                acc[mt][nt][2] = h2; acc[mt][nt][3] = h3;
                sB  += h2*h2 + h3*h3;
                dVB += en.x*h2 + en.y*h3;
                dHB += en.x*ho.x + en.y*ho.y;
                dKB += en.x*ky.x + en.y*ky.y;
            }
            #pragma unroll
            for (int o = 1; o <= 2; o <<= 1) {
                sA  += __shfl_xor_sync(0xffffffffu, sA,  o);
                sB  += __shfl_xor_sync(0xffffffffu, sB,  o);
                dVA += __shfl_xor_sync(0xffffffffu, dVA, o);
                dVB += __shfl_xor_sync(0xffffffffu, dVB, o);
                dHA += __shfl_xor_sync(0xffffffffu, dHA, o);
                dHB += __shfl_xor_sync(0xffffffffu, dHB, o);
                dKA += __shfl_xor_sync(0xffffffffu, dKA, o);
                dKB += __shfl_xor_sync(0xffffffffu, dKB, o);
            }
            if ((lane & 3) == 0) {
                atomicAdd(&rs[rA], sA);  atomicAdd(&rs[rB], sB);
                atomicAdd(&dV[rA], dVA); atomicAdd(&dV[rB], dVB);
                atomicAdd(&dH[rA], dHA); atomicAdd(&dH[rB], dHB);
                atomicAdd(&dK[rA], dKA); atomicAdd(&dK[rB], dKB);
            }
        }
        __syncthreads();
        if (tid < 128) {
            float r = rsqrtf(fmaxf(rs[tid], 1e-12f));
            rs[tid] = r;
            gn[tid] = (acts[tid] ? dV[tid]*r : dH[tid]) + dK[tid];
        }
        __syncthreads();

        // ---------- epilogue pass 2: normalize + write h / bf16 hi/lo ----------
        #pragma unroll
        for (int mt = 0; mt < 2; mt++) {
            int rA = warp_m*32 + mt*16 + (lane >> 2);
            int rB = rA + 8;
            float rnA = rs[rA], rnB = rs[rB];
            int aA = acts[rA], aB = acts[rB];
            size_t gOA = (size_t)(rowBase + rA)*ND;
            size_t gOB = (size_t)(rowBase + rB)*ND;
            #pragma unroll
            for (int nt = 0; nt < 8; nt++) {
                int col = warp_n*64 + nt*8 + 2*(lane & 3);
                if (aA || first) {
                    float v0 = aA ? acc[mt][nt][0]*rnA : 0.f;
                    float v1 = aA ? acc[mt][nt][1]*rnA : 0.f;
                    *(float2*)(h + gOA + col) = make_float2(v0, v1);
                    __nv_bfloat16 h0 = __float2bfloat16(v0), h1 = __float2bfloat16(v1);
                    *(__nv_bfloat162*)(g_hA_hi + gOA + col) = __nv_bfloat162(h0, h1);
                    *(__nv_bfloat162*)(g_hA_lo + gOA + col) = __nv_bfloat162(
                        __float2bfloat16(v0 - __bfloat162float(h0)),
                        __float2bfloat16(v1 - __bfloat162float(h1)));
                }
                if (aB || first) {
                    float v0 = aB ? acc[mt][nt][2]*rnB : 0.f;
                    float v1 = aB ? acc[mt][nt][3]*rnB : 0.f;
                    *(float2*)(h + gOB + col) = make_float2(v0, v1);
                    __nv_bfloat16 h0 = __float2bfloat16(v0), h1 = __float2bfloat16(v1);
                    *(__nv_bfloat162*)(g_hA_hi + gOB + col) = __nv_bfloat162(h0, h1);
                    *(__nv_bfloat162*)(g_hA_lo + gOB + col) = __nv_bfloat162(
                        __float2bfloat16(v0 - __bfloat162float(h0)),
                        __float2bfloat16(v1 - __bfloat162float(h1)));
                }
            }
        }
    }
}

// ===================== launch =====================
extern "C" void kernel_launch(void* const* d_in, const int* in_sizes, int n_in,
                              void* d_out, int out_size) {
    const int*   tok  = (const int*)  d_in[0];
    const float* mask = (const float*)d_in[1];
    const float* keys = (const float*)d_in[2];
    const float* emb  = (const float*)d_in[3];
    const float* U    = (const float*)d_in[4];
    const float* V    = (const float*)d_in[5];
    const float* W    = (const float*)d_in[6];
    float* h = (float*)d_out;

    cudaFuncSetAttribute(steps_kernel, cudaFuncAttributeMaxDynamicSharedMemorySize, SMEM_BYTES);
    cudaFuncSetAttribute(hmma_gemm0,   cudaFuncAttributeMaxDynamicSharedMemorySize, SMEM_BYTES);

    encode_kernel<<<NB*NS, 256>>>(tok, mask, emb);
    prep_bt_all<<<3*ND, ND>>>(U, V, W);
    split_kernel<<<(NB*NE*ND + NB*NS*ND)/256, 256>>>(keys);   // keys + enc (enc after encode)
    hmma_gemm0<<<192, 512, SMEM_BYTES>>>();
    steps_kernel<<<128, 512, SMEM_BYTES>>>(keys, h);
}

// round 7
// speedup vs baseline: 1.1366x; 1.1366x over previous
#include <cuda_runtime.h>
#include <cuda_bf16.h>
#include <cstdint>
#include <math.h>

#define NB 256
#define NS 32
#define NL 32
#define ND 256
#define NE 64
#define KBIG 768          // Bt columns: [Hi | Lo | Hi-dup(unused now)]

// ===================== scratch (device globals; no runtime alloc) =====================
__device__ float g_enc[NB*NS*ND];            // enc[b,s,d]
__device__ float g_eW [NB*NS*ND];            // enc @ W
__device__ float g_kV [NB*NE*ND];            // keys @ V
__device__ int   g_act[NB*NS];
__device__ __nv_bfloat16 g_Ut[ND*KBIG];      // U^T  [Hi|Lo|Hi]
__device__ __nv_bfloat16 g_Vt[ND*KBIG];      // V^T  [Hi|Lo|Hi]
__device__ __nv_bfloat16 g_Wt[ND*KBIG];      // W^T  [Hi|Lo|Hi]
__device__ __nv_bfloat16 g_kyhi[NB*NE*ND];   // keys split
__device__ __nv_bfloat16 g_kylo[NB*NE*ND];
__device__ __nv_bfloat16 g_enhi[NB*NS*ND];   // enc split
__device__ __nv_bfloat16 g_enlo[NB*NS*ND];
__device__ __nv_bfloat16 g_hA_hi[NB*NE*ND];  // h split hi (row,k)
__device__ __nv_bfloat16 g_hA_lo[NB*NE*ND];  // h split lo

// ===================== PTX wrappers =====================
__device__ __forceinline__ uint32_t smem_u32(const void* p) {
    uint32_t a;
    asm("{ .reg .u64 t; cvta.to.shared.u64 t, %1; cvt.u32.u64 %0, t; }" : "=r"(a) : "l"(p));
    return a;
}
__device__ __forceinline__ void cpa16(uint32_t dst, const void* src) {
    asm volatile("cp.async.cg.shared.global [%0], [%1], 16;" :: "r"(dst), "l"(src));
}
#define CP_COMMIT() asm volatile("cp.async.commit_group;" ::: "memory")
#define CP_WAIT1()  asm volatile("cp.async.wait_group 1;"  ::: "memory")
#define CP_WAIT0()  asm volatile("cp.async.wait_group 0;"  ::: "memory")

__device__ __forceinline__ void ldsm_x4(uint32_t* r, uint32_t addr) {
    asm volatile("ldmatrix.sync.aligned.m8n8.x4.shared.b16 {%0,%1,%2,%3}, [%4];"
        : "=r"(r[0]), "=r"(r[1]), "=r"(r[2]), "=r"(r[3]) : "r"(addr));
}
__device__ __forceinline__ void ldsm_x2(uint32_t* r, uint32_t addr) {
    asm volatile("ldmatrix.sync.aligned.m8n8.x2.shared.b16 {%0,%1}, [%2];"
        : "=r"(r[0]), "=r"(r[1]) : "r"(addr));
}
__device__ __forceinline__ void mma_bf16(float* d, const uint32_t* a, const uint32_t* b) {
    asm volatile("mma.sync.aligned.m16n8k16.row.col.f32.bf16.bf16.f32 "
        "{%0,%1,%2,%3}, {%4,%5,%6,%7}, {%8,%9}, {%0,%1,%2,%3};"
        : "+f"(d[0]), "+f"(d[1]), "+f"(d[2]), "+f"(d[3])
        : "r"(a[0]), "r"(a[1]), "r"(a[2]), "r"(a[3]), "r"(b[0]), "r"(b[1]));
}

// ===================== steps smem layout (80B row stride, k32 chunks) ===============
#define STG_B   20480                      // B tile: 256 rows * 80B
#define STG_AH  10240                      // A tile: 128 rows * 80B
#define STG     40960
#define SM_DOTEK 0                         // 128*32 floats = 16384
#define SM_GATE 16384
#define SM_RSQ  16896
#define SM_DV   17408
#define SM_DH   17920
#define SM_GN   18432
#define SM_ACTS 18944
#define SM_ST0  19456
#define SMEM_STEPS (SM_ST0 + 3*STG)        // 142336

// ===================== gemm0 smem layout (144B stride, k64 chunks) ==================
#define G_A_TILE 18432
#define G_B_TILE 36864
#define G_STAGE  55296
#define SMEM_G0  (3*G_STAGE)               // 165888

// ===================== encode (vectorized) =====================
__global__ __launch_bounds__(256)
void encode_kernel(const int* __restrict__ tok, const float* __restrict__ mask,
                   const float* __restrict__ emb) {
    __shared__ float4 red[4][64];
    const int bs = blockIdx.x, tid = threadIdx.x;
    const int lg = tid >> 6, d4 = tid & 63;
    const int*   t = tok  + (size_t)bs*NL;
    const float* m = mask + (size_t)bs*NL;

    if (tid < 32) {
        float mv = m[tid];
        #pragma unroll
        for (int o = 16; o > 0; o >>= 1) mv += __shfl_xor_sync(0xffffffffu, mv, o);
        if (tid == 0) g_act[bs] = (mv > 0.f) ? 1 : 0;
    }

    float4 acc = make_float4(0.f, 0.f, 0.f, 0.f);
    #pragma unroll
    for (int i = 0; i < 8; i++) {
        int l = lg*8 + i;
        float mv = __ldg(m + l);
        int   tv = __ldg(t + l);
        float4 e = __ldg((const float4*)(emb + (size_t)tv*ND) + d4);
        acc.x += mv*e.x; acc.y += mv*e.y; acc.z += mv*e.z; acc.w += mv*e.w;
    }
    red[lg][d4] = acc;
    __syncthreads();
    if (lg == 0) {
        float4 a = red[0][d4], b = red[1][d4], c = red[2][d4], d = red[3][d4];
        ((float4*)(g_enc + (size_t)bs*ND))[d4] =
            make_float4(a.x+b.x+c.x+d.x, a.y+b.y+c.y+d.y, a.z+b.z+c.z+d.z, a.w+b.w+c.w+d.w);
    }
}

// ===================== prep: Mt[n][k] = [Mhi^T | Mlo^T | Mhi^T] =====================
__global__ void prep_bt_all(const float* __restrict__ U, const float* __restrict__ V,
                            const float* __restrict__ W) {
    int n = blockIdx.x & 255, which = blockIdx.x >> 8, k = threadIdx.x;
    const float* M = (which == 0) ? U : (which == 1) ? V : W;
    __nv_bfloat16* out = (which == 0) ? g_Ut : (which == 1) ? g_Vt : g_Wt;
    float v = M[(size_t)k*ND + n];
    __nv_bfloat16 hi = __float2bfloat16(v);
    __nv_bfloat16 lo = __float2bfloat16(v - __bfloat162float(hi));
    out[(size_t)n*KBIG + k]       = hi;
    out[(size_t)n*KBIG + 256 + k] = lo;
    out[(size_t)n*KBIG + 512 + k] = hi;
}

// ===================== split fp32 -> bf16 hi/lo (keys and enc) =====================
__global__ void split_kernel(const float* __restrict__ keys) {
    int i = blockIdx.x * blockDim.x + threadIdx.x;
    const int NK = NB*NE*ND;
    float v; __nv_bfloat16 *ph, *pl; int idx;
    if (i < NK) { v = keys[i]; ph = g_kyhi; pl = g_kylo; idx = i; }
    else        { idx = i - NK; v = g_enc[idx]; ph = g_enhi; pl = g_enlo; }
    __nv_bfloat16 h = __float2bfloat16(v);
    ph[idx] = h;
    pl[idx] = __float2bfloat16(v - __bfloat162float(h));
}

// ===================== HMMA prelude GEMM: kV = keys@V and eW = enc@W ================
__global__ void __launch_bounds__(512, 1)
hmma_gemm0() {
    extern __shared__ char smem[];
    const uint32_t sb = smem_u32(smem);
    const int tid  = threadIdx.x;
    const int lane = tid & 31;
    const int wid  = tid >> 5;
    const int warp_m = wid >> 2, warp_n = wid & 3;
    const int bx = blockIdx.x;

    const __nv_bfloat16 *Ahi, *Alo, *Bt; float* C; int rowBase;
    if (bx < 128) { Ahi = g_kyhi; Alo = g_kylo; Bt = g_Vt; C = g_kV; rowBase = bx*128; }
    else          { Ahi = g_enhi; Alo = g_enlo; Bt = g_Wt; C = g_eW; rowBase = (bx-128)*128; }
    const __nv_bfloat16* hi = Ahi + (size_t)rowBase*ND;
    const __nv_bfloat16* lo = Alo + (size_t)rowBase*ND;

    const int selA = lane >> 3;
    const uint32_t aoff = (uint32_t)(((selA & 1)*8 + (lane & 7))*144 + (selA >> 1)*16);
    const int l16 = lane & 15;
    const uint32_t boff = (uint32_t)((l16 & 7)*144 + (l16 >> 3)*16);

    auto load_chunk = [&](int c, int slot) {
        const __nv_bfloat16* asrc = ((c < 8) ? hi : lo) + (c & 3)*64;
        const __nv_bfloat16* bsrc = Bt + c*64;
        uint32_t adst = sb + (uint32_t)slot*G_STAGE;
        uint32_t bdst = adst + G_A_TILE;
        #pragma unroll
        for (int i = 0; i < 2; i++) {
            int idx = tid + i*512, row = idx >> 3, seg = idx & 7;
            cpa16(adst + row*144 + seg*16, asrc + (size_t)row*ND + seg*8);
        }
        #pragma unroll
        for (int i = 0; i < 4; i++) {
            int idx = tid + i*512, n = idx >> 3, seg = idx & 7;
            cpa16(bdst + n*144 + seg*16, bsrc + (size_t)n*KBIG + seg*8);
        }
    };

    float acc[2][8][4];
    #pragma unroll
    for (int mt = 0; mt < 2; mt++)
        #pragma unroll
        for (int nt = 0; nt < 8; nt++)
            #pragma unroll
            for (int q = 0; q < 4; q++) acc[mt][nt][q] = 0.f;

    load_chunk(0, 0); CP_COMMIT();
    load_chunk(1, 1); CP_COMMIT();
    #pragma unroll
    for (int c = 0; c < 12; ++c) {
        if (c < 11) CP_WAIT1(); else CP_WAIT0();
        __syncthreads();
        if (c < 10) { load_chunk(c + 2, (c + 2) % 3); CP_COMMIT(); }
        const uint32_t base = sb + (uint32_t)(c % 3)*G_STAGE;
        const uint32_t abase = base + (warp_m*32)*144 + aoff;
        const uint32_t bbase = base + G_A_TILE + (warp_n*64)*144 + boff;
        #pragma unroll
        for (int k4 = 0; k4 < 4; ++k4) {
            const uint32_t kb = k4 * 32;
            uint32_t a0[4], a1[4];
            ldsm_x4(a0, abase + kb);
            ldsm_x4(a1, abase + 16*144 + kb);
            #pragma unroll
            for (int nt = 0; nt < 8; ++nt) {
                uint32_t bfrag[2];
                ldsm_x2(bfrag, bbase + nt*8*144 + kb);
                mma_bf16(acc[0][nt], a0, bfrag);
                mma_bf16(acc[1][nt], a1, bfrag);
            }
        }
        __syncthreads();
    }

    #pragma unroll
    for (int mt = 0; mt < 2; mt++) {
        int rA = warp_m*32 + mt*16 + (lane >> 2);
        int rB = rA + 8;
        size_t gOA = (size_t)(rowBase + rA)*ND;
        size_t gOB = (size_t)(rowBase + rB)*ND;
        #pragma unroll
        for (int nt = 0; nt < 8; nt++) {
            int col = warp_n*64 + nt*8 + 2*(lane & 3);
            *(float2*)(C + gOA + col) = make_float2(acc[mt][nt][0], acc[mt][nt][1]);
            *(float2*)(C + gOB + col) = make_float2(acc[mt][nt][2], acc[mt][nt][3]);
        }
    }
}

// ===================== persistent fused recurrence =====================
__global__ void __launch_bounds__(512, 1)
steps_kernel(const float* __restrict__ keys, float* __restrict__ h) {
    extern __shared__ char smem[];
    const uint32_t sb = smem_u32(smem);
    const int tid    = threadIdx.x;
    const int lane   = tid & 31;
    const int wid    = tid >> 5;
    const int warp_m = wid >> 2;          // 0..3 -> 32 rows
    const int warp_n = wid & 3;           // 0..3 -> 64 cols
    const int rowBase = blockIdx.x * 128;

    float* dek  = (float*)(smem + SM_DOTEK);
    float* gs   = (float*)(smem + SM_GATE);
    float* rs   = (float*)(smem + SM_RSQ);
    float* dV   = (float*)(smem + SM_DV);
    float* dH   = (float*)(smem + SM_DH);
    float* gn   = (float*)(smem + SM_GN);
    int*   acts = (int*)  (smem + SM_ACTS);

    // ---------- phase 0: dotEK[s][r] = dot(enc_s, keys_row) once ----------
    {
        int r = tid >> 2, part = tid & 3;
        int grow = rowBase + r, b = grow >> 6;
        float4 ky[16];
        const float4* kp = (const float4*)(keys + (size_t)grow*ND + part*64);
        #pragma unroll
        for (int i = 0; i < 16; i++) ky[i] = kp[i];
        for (int s = 0; s < NS; s++) {
            const float4* ep = (const float4*)(g_enc + ((size_t)b*NS + s)*ND + part*64);
            float d = 0.f;
            #pragma unroll
            for (int i = 0; i < 16; i++) {
                float4 e = ep[i];
                d += ky[i].x*e.x + ky[i].y*e.y + ky[i].z*e.z + ky[i].w*e.w;
            }
            d += __shfl_xor_sync(0xffffffffu, d, 1);
            d += __shfl_xor_sync(0xffffffffu, d, 2);
            if (part == 0) dek[s*128 + r] = d;
        }
        if (tid < 128) gn[tid] = 0.f;
    }

    const __nv_bfloat16* hi = g_hA_hi + (size_t)rowBase*ND;
    const __nv_bfloat16* lo = g_hA_lo + (size_t)rowBase*ND;

    // ldmatrix per-lane offsets (80B row stride)
    const int selA = lane >> 3;
    const uint32_t aoff  = (uint32_t)(((selA & 1)*8 + (lane & 7))*80 + (selA >> 1)*16);
    const uint32_t boff4 = (uint32_t)(((lane >> 4)*8 + (lane & 7))*80 + ((lane >> 3) & 1)*16);

    float acc[2][8][4];

    // q 0..7: B = Hi[q*32], A = hi+lo sweep; q 8..15: B = Lo[(q-8)*32], A = hi
    auto load_chunk = [&](int q, int slot) {
        int kk = (q & 7) * 32;
        const __nv_bfloat16* bsrc = g_Ut + ((q < 8) ? kk : (256 + kk));
        uint32_t base = sb + SM_ST0 + (uint32_t)slot*STG;
        #pragma unroll
        for (int i = 0; i < 2; i++) {          // B: 256 rows x 4 segs
            int idx = tid + i*512, row = idx >> 2, seg = idx & 3;
            cpa16(base + row*80 + seg*16, bsrc + (size_t)row*KBIG + seg*8);
        }
        {                                      // A hi: 128 rows x 4 segs
            int row = tid >> 2, seg = tid & 3;
            cpa16(base + STG_B + row*80 + seg*16, hi + (size_t)row*ND + kk + seg*8);
        }
        if (q < 8) {                           // A lo
            int row = tid >> 2, seg = tid & 3;
            cpa16(base + STG_B + STG_AH + row*80 + seg*16, lo + (size_t)row*ND + kk + seg*8);
        }
    };

    auto compute = [&](int q) {
        uint32_t base = sb + SM_ST0 + (uint32_t)(q % 3)*STG;
        uint32_t bB = base + (warp_n*64)*80 + boff4;
        uint32_t aH = base + STG_B + (warp_m*32)*80 + aoff;
        uint32_t aL = aH + STG_AH;
        #pragma unroll
        for (int k2 = 0; k2 < 2; k2++) {
            uint32_t kb = (uint32_t)k2*32;
            uint32_t bq[16];
            #pragma unroll
            for (int np = 0; np < 4; np++) ldsm_x4(&bq[np*4], bB + np*1280 + kb);
            uint32_t ah[8];
            ldsm_x4(ah,     aH + kb);
            ldsm_x4(ah + 4, aH + 16*80 + kb);
            #pragma unroll
            for (int np = 0; np < 4; np++) {
                mma_bf16(acc[0][2*np],   ah,     &bq[np*4]);
                mma_bf16(acc[0][2*np+1], ah,     &bq[np*4+2]);
                mma_bf16(acc[1][2*np],   ah + 4, &bq[np*4]);
                mma_bf16(acc[1][2*np+1], ah + 4, &bq[np*4+2]);
            }
            if (q < 8) {
                uint32_t al[8];
                ldsm_x4(al,     aL + kb);
                ldsm_x4(al + 4, aL + 16*80 + kb);
                #pragma unroll
                for (int np = 0; np < 4; np++) {
                    mma_bf16(acc[0][2*np],   al,     &bq[np*4]);
                    mma_bf16(acc[0][2*np+1], al,     &bq[np*4+2]);
                    mma_bf16(acc[1][2*np],   al + 4, &bq[np*4]);
                    mma_bf16(acc[1][2*np+1], al + 4, &bq[np*4+2]);
                }
            }
        }
    };

    for (int s = 0; s < NS; ++s) {
        const bool first = (s == 0);
        const bool last  = (s == NS - 1);
        __syncthreads();                  // prev pass2 / phase0 done
        if (tid < 128) {
            int grow = rowBase + tid;
            int b = grow >> 6;
            gs[tid]   = 1.f / (1.f + expf(-(gn[tid] + dek[s*128 + tid])));
            acts[tid] = g_act[b*NS + s];
            rs[tid] = 0.f; dV[tid] = 0.f; dH[tid] = 0.f;
        }

        #pragma unroll
        for (int mt = 0; mt < 2; mt++)
            #pragma unroll
            for (int nt = 0; nt < 8; nt++)
                #pragma unroll
                for (int q = 0; q < 4; q++) acc[mt][nt][q] = 0.f;

        if (!first) {
            load_chunk(0, 0); CP_COMMIT();
            load_chunk(1, 1); CP_COMMIT();
            for (int q = 0; q < 16; ++q) {
                if (q < 15) CP_WAIT1(); else CP_WAIT0();
                __syncthreads();
                if (q < 14) { load_chunk(q + 2, (q + 2) % 3); CP_COMMIT(); }
                compute(q);
            }
        } else {
            __syncthreads();
        }

        // ---------- epilogue pass 1 ----------
        const int sn = (s + 1 < NS) ? s + 1 : NS - 1;
        #pragma unroll
        for (int mt = 0; mt < 2; mt++) {
            int rA = warp_m*32 + mt*16 + (lane >> 2);
            int rB = rA + 8;
            int gA = rowBase + rA, gB = rowBase + rB;
            int bA = gA >> 6;
            const float* kvA = g_kV + (size_t)gA*ND;
            const float* kvB = g_kV + (size_t)gB*ND;
            const float* ewR = g_eW  + ((size_t)bA*NS + s )*ND;
            const float* enN = g_enc + ((size_t)bA*NS + sn)*ND;
            float gateA = gs[rA], gateB = gs[rB];
            float sA = 0.f, sB = 0.f;
            float dVA = 0.f, dVB = 0.f, dHA = 0.f, dHB = 0.f;
            #pragma unroll
            for (int nt = 0; nt < 8; nt++) {
                int col = warp_n*64 + nt*8 + 2*(lane & 3);
                float2 en = *(const float2*)(enN + col);
                float2 ew = *(const float2*)(ewR + col);
                float2 kv, ho;
                kv = *(const float2*)(kvA + col);
                if (first) ho = make_float2(0.f, 0.f);
                else {
                    __nv_bfloat162 hb = *(const __nv_bfloat162*)(g_hA_hi + (size_t)gA*ND + col);
                    __nv_bfloat162 lb = *(const __nv_bfloat162*)(g_hA_lo + (size_t)gA*ND + col);
                    ho = make_float2(__bfloat162float(hb.x) + __bfloat162float(lb.x),
                                     __bfloat162float(hb.y) + __bfloat162float(lb.y));
                }
                float v0 = fmaxf(acc[mt][nt][0] + kv.x + ew.x, 0.f);
                float v1 = fmaxf(acc[mt][nt][1] + kv.y + ew.y, 0.f);
                float h0 = ho.x + gateA*v0, h1 = ho.y + gateA*v1;
                acc[mt][nt][0] = h0; acc[mt][nt][1] = h1;
                sA  += h0*h0 + h1*h1;
                dVA += en.x*h0 + en.y*h1;
                dHA += en.x*ho.x + en.y*ho.y;
                kv = *(const float2*)(kvB + col);
                if (first) ho = make_float2(0.f, 0.f);
                else {
                    __nv_bfloat162 hb = *(const __nv_bfloat162*)(g_hA_hi + (size_t)gB*ND + col);
                    __nv_bfloat162 lb = *(const __nv_bfloat162*)(g_hA_lo + (size_t)gB*ND + col);
                    ho = make_float2(__bfloat162float(hb.x) + __bfloat162float(lb.x),
                                     __bfloat162float(hb.y) + __bfloat162float(lb.y));
                }
                float w0 = fmaxf(acc[mt][nt][2] + kv.x + ew.x, 0.f);
                float w1 = fmaxf(acc[mt][nt][3] + kv.y + ew.y, 0.f);
                float h2 = ho.x + gateB*w0, h3 = ho.y + gateB*w1;
                acc[mt][nt][2] = h2; acc[mt][nt][3] = h3;
                sB  += h2*h2 + h3*h3;
                dVB += en.x*h2 + en.y*h3;
                dHB += en.x*ho.x + en.y*ho.y;
            }
            #pragma unroll
            for (int o = 1; o <= 2; o <<= 1) {
                sA  += __shfl_xor_sync(0xffffffffu, sA,  o);
                sB  += __shfl_xor_sync(0xffffffffu, sB,  o);
                dVA += __shfl_xor_sync(0xffffffffu, dVA, o);
                dVB += __shfl_xor_sync(0xffffffffu, dVB, o);
                dHA += __shfl_xor_sync(0xffffffffu, dHA, o);
                dHB += __shfl_xor_sync(0xffffffffu, dHB, o);
            }
            if ((lane & 3) == 0) {
                atomicAdd(&rs[rA], sA);  atomicAdd(&rs[rB], sB);
                atomicAdd(&dV[rA], dVA); atomicAdd(&dV[rB], dVB);
                atomicAdd(&dH[rA], dHA); atomicAdd(&dH[rB], dHB);
            }
        }
        __syncthreads();
        if (tid < 128) {
            float r = rsqrtf(fmaxf(rs[tid], 1e-12f));
            rs[tid] = r;
            gn[tid] = acts[tid] ? dV[tid]*r : dH[tid];
        }
        __syncthreads();

        // ---------- epilogue pass 2: normalize + write bf16 hi/lo (+h at last) -------
        #pragma unroll
        for (int mt = 0; mt < 2; mt++) {
            int rA = warp_m*32 + mt*16 + (lane >> 2);
            int rB = rA + 8;
            float rn2[2] = { rs[rA], rs[rB] };
            int   ac2[2] = { acts[rA], acts[rB] };
            size_t gO2[2] = { (size_t)(rowBase + rA)*ND, (size_t)(rowBase + rB)*ND };
            #pragma unroll
            for (int half = 0; half < 2; half++) {
                float rn = rn2[half]; int aa = ac2[half]; size_t gO = gO2[half];
                #pragma unroll
                for (int nt = 0; nt < 8; nt++) {
                    int col = warp_n*64 + nt*8 + 2*(lane & 3);
                    float a0 = acc[mt][nt][half*2], a1 = acc[mt][nt][half*2+1];
                    if (aa || first) {
                        float v0 = aa ? a0*rn : 0.f;
                        float v1 = aa ? a1*rn : 0.f;
                        __nv_bfloat16 h0 = __float2bfloat16(v0), h1 = __float2bfloat16(v1);
                        *(__nv_bfloat162*)(g_hA_hi + gO + col) = __nv_bfloat162(h0, h1);
                        *(__nv_bfloat162*)(g_hA_lo + gO + col) = __nv_bfloat162(
                            __float2bfloat16(v0 - __bfloat162float(h0)),
                            __float2bfloat16(v1 - __bfloat162float(h1)));
                        if (last) *(float2*)(h + gO + col) = make_float2(v0, v1);
                    } else if (last) {
                        __nv_bfloat162 hb = *(const __nv_bfloat162*)(g_hA_hi + gO + col);
                        __nv_bfloat162 lb = *(const __nv_bfloat162*)(g_hA_lo + gO + col);
                        *(float2*)(h + gO + col) = make_float2(
                            __bfloat162float(hb.x) + __bfloat162float(lb.x),
                            __bfloat162float(hb.y) + __bfloat162float(lb.y));
                    }
                }
            }
        }
    }
}

// ===================== launch =====================
extern "C" void kernel_launch(void* const* d_in, const int* in_sizes, int n_in,
                              void* d_out, int out_size) {
    const int*   tok  = (const int*)  d_in[0];
    const float* mask = (const float*)d_in[1];
    const float* keys = (const float*)d_in[2];
    const float* emb  = (const float*)d_in[3];
    const float* U    = (const float*)d_in[4];
    const float* V    = (const float*)d_in[5];
    const float* W    = (const float*)d_in[6];
    float* h = (float*)d_out;

    cudaFuncSetAttribute(steps_kernel, cudaFuncAttributeMaxDynamicSharedMemorySize, SMEM_STEPS);
    cudaFuncSetAttribute(hmma_gemm0,   cudaFuncAttributeMaxDynamicSharedMemorySize, SMEM_G0);

    encode_kernel<<<NB*NS, 256>>>(tok, mask, emb);
    prep_bt_all<<<3*ND, ND>>>(U, V, W);
    split_kernel<<<(NB*NE*ND + NB*NS*ND)/256, 256>>>(keys);
    hmma_gemm0<<<192, 512, SMEM_G0>>>();
    steps_kernel<<<128, 512, SMEM_STEPS>>>(keys, h);
}